// round 12
// baseline (speedup 1.0000x reference)
#include <cuda_runtime.h>
#include <cuda_fp16.h>
#include <cstdint>

#define BB   128
#define SSEQ 513
#define HH   256
#define SSH  (SSEQ * HH)

#define NW    (5 * HH * HH)
#define NW16  (NW / 16)              // 20,480
#define NCVT  (NW16 + 32)

__device__ __half gw[NW];            // [widx][n][h] fp16
__device__ float  gbsum[HH];         // sum of 5 bias vectors

// ---------------- fused GEMM tiling ----------------
// X resident in smem: 128 rows x 256 fp16, 528B row stride (512 + 16 pad)
#define XROWB 528
#define XSMB  (128 * XROWB)          // 67584
// W ring: k=64 tiles, 128 rows x 144B, 2 stages
#define KT    64
#define NKT   4
#define ROWB  144
#define TILEB (128 * ROWB)           // 18432
#define SMTOT (XSMB + 2 * TILEB)     // 104448

__device__ __forceinline__ uint32_t smem_u32(const void* p) {
    uint32_t a;
    asm("{ .reg .u64 t; cvta.to.shared.u64 t, %1; cvt.u32.u64 %0, t; }" : "=r"(a) : "l"(p));
    return a;
}
__device__ __forceinline__ void cpasync16(uint32_t dst, const void* src) {
    asm volatile("cp.async.ca.shared.global [%0], [%1], 16;" :: "r"(dst), "l"(src));
}
__device__ __forceinline__ void cp_commit() { asm volatile("cp.async.commit_group;"); }
__device__ __forceinline__ void cp_wait0()  { asm volatile("cp.async.wait_group 0;"); }
__device__ __forceinline__ void ldsm_x4(uint32_t* r, uint32_t addr) {
    asm volatile("ldmatrix.sync.aligned.m8n8.x4.shared.b16 {%0,%1,%2,%3}, [%4];"
                 : "=r"(r[0]), "=r"(r[1]), "=r"(r[2]), "=r"(r[3]) : "r"(addr));
}
__device__ __forceinline__ void mma_f16(float* d, const uint32_t* a, uint32_t b0, uint32_t b1) {
    asm volatile(
        "mma.sync.aligned.m16n8k16.row.col.f32.f16.f16.f32 "
        "{%0,%1,%2,%3}, {%4,%5,%6,%7}, {%8,%9}, {%0,%1,%2,%3};"
        : "+f"(d[0]), "+f"(d[1]), "+f"(d[2]), "+f"(d[3])
        : "r"(a[0]), "r"(a[1]), "r"(a[2]), "r"(a[3]), "r"(b0), "r"(b1));
}
__device__ __forceinline__ uint2 f4_to_h4(float4 v) {
    __half2 h0 = __floats2half2_rn(v.x, v.y);
    __half2 h1 = __floats2half2_rn(v.z, v.w);
    uint2 u;
    u.x = *reinterpret_cast<uint32_t*>(&h0);
    u.y = *reinterpret_cast<uint32_t*>(&h1);
    return u;
}

// ---- kernel 1: W fp32->fp16 + bias presum (tiny: 1.3MB) ----
__global__ __launch_bounds__(256)
void cvtw_kernel(const float* __restrict__ W, const float* __restrict__ bias)
{
    const uint32_t id = blockIdx.x * 256 + threadIdx.x;
    if (id < NW16) {
        const size_t f = (size_t)id * 16;
        const float4* wp = reinterpret_cast<const float4*>(W + f);
        float4 v0 = wp[0], v1 = wp[1], v2 = wp[2], v3 = wp[3];
        uint2 a = f4_to_h4(v0), b = f4_to_h4(v1);
        uint2 c = f4_to_h4(v2), d = f4_to_h4(v3);
        uint4* op = reinterpret_cast<uint4*>(&gw[f]);
        op[0] = make_uint4(a.x, a.y, b.x, b.y);
        op[1] = make_uint4(c.x, c.y, d.x, d.y);
    } else if (id < NCVT) {
        const int t = (int)(id - NW16);
        #pragma unroll
        for (int j = 0; j < 8; ++j) {
            const int c = t * 8 + j;
            float v = 0.0f;
            #pragma unroll
            for (int l = 0; l < 5; ++l) v += bias[l * HH + c];
            gbsum[c] = v;
        }
    }
}

// ---- fused kernel: in-CTA x convert (resident X) + fp16 GEMM with W ring ----
// CTA (n-half, s): out[0:128, s, n0:n0+128] = x[:,s,:] @ W[idx]^T + bsum
__global__ __launch_bounds__(256, 2)
void pmha_fused_kernel(const float* __restrict__ x, float* __restrict__ out)
{
    extern __shared__ char smem[];
    const uint32_t sb = smem_u32(smem);
    const uint32_t wbase = sb + XSMB;
    const int tid  = threadIdx.x;
    const int lane = tid & 31;
    const int wid  = tid >> 5;
    const int tg   = lane >> 2;
    const int tig  = lane & 3;
    const int wm   = (wid >> 2) * 64;
    const int wn   = (wid & 3) * 32;
    const int s    = blockIdx.y;
    const int n0   = blockIdx.x * 128;
    const int widx = (s < 3) ? s : ((s & 1) ? 3 : 4);

    const float*  xsrc = x  + (size_t)s * HH;                    // row b at + b*SSH
    const __half* Wp   = gw + (size_t)widx * (HH * HH) + (size_t)n0 * HH;

    // W prefetch: 128 rows x 8 chunks(16B); 4 per thread
    const int prow = tid >> 3;
    const int pc   = tid & 7;
    auto prefetchW = [&](int kt) {
        const int k0 = kt * KT;
        const uint32_t base = wbase + (kt & 1) * TILEB;
        #pragma unroll
        for (int t = 0; t < 4; ++t) {
            const int row = prow + t * 32;
            cpasync16(base + (uint32_t)row * ROWB + (uint32_t)pc * 16,
                      Wp + (size_t)row * HH + k0 + pc * 8);
        }
    };

    prefetchW(0); cp_commit();   // W tile 0 loads during the X conversion below

    // ---- one-time X conversion: 128x256 fp32 -> resident fp16 smem ----
    // pass p: 4 rows (64 threads each), warp = contiguous 512B read
    {
        const int crow = tid >> 6;          // 0..3
        const int cc4  = tid & 63;          // float4 col 0..63
        #pragma unroll 4
        for (int p = 0; p < 32; ++p) {
            const int row = p * 4 + crow;
            float4 v = *reinterpret_cast<const float4*>(xsrc + (size_t)row * SSH + cc4 * 4);
            *reinterpret_cast<uint2*>(smem + (uint32_t)row * XROWB + (uint32_t)cc4 * 8) = f4_to_h4(v);
        }
    }

    // ldmatrix base addresses
    const int lr = lane & 15;
    const int lc = lane >> 4;
    uint32_t aA[4], aB[2];
    #pragma unroll
    for (int i = 0; i < 4; ++i)
        aA[i] = sb + (uint32_t)(wm + i * 16 + lr) * XROWB + lc * 16;
    #pragma unroll
    for (int jj = 0; jj < 2; ++jj)
        aB[jj] = wbase + (uint32_t)(wn + jj * 16 + lr) * ROWB + lc * 16;

    float acc[4][4][4] = {};

    for (int kt = 0; kt < NKT; ++kt) {
        cp_wait0();
        __syncthreads();     // first iter also publishes the X conversion

        if (kt + 1 < NKT) { prefetchW(kt + 1); cp_commit(); }

        const uint32_t wst = (kt & 1) * TILEB;
        const uint32_t xkt = (uint32_t)kt * 128;   // 64 fp16 = 128B per k-tile
        #pragma unroll
        for (int ks = 0; ks < 4; ++ks) {
            uint32_t a[4][4], b[2][4];
            #pragma unroll
            for (int i = 0; i < 4; ++i) ldsm_x4(a[i], aA[i] + xkt + ks * 32);
            #pragma unroll
            for (int jj = 0; jj < 2; ++jj) ldsm_x4(b[jj], aB[jj] + wst + ks * 32);
            #pragma unroll
            for (int i = 0; i < 4; ++i)
                #pragma unroll
                for (int j = 0; j < 4; ++j) {
                    const int jj = j >> 1, sel = j & 1;
                    mma_f16(acc[i][j], a[i], b[jj][sel], b[jj][sel + 2]);
                }
        }
    }

    // epilogue: bias cached in registers, float2 stores
    float bA[4], bB[4];
    #pragma unroll
    for (int j = 0; j < 4; ++j) {
        const int c = wn + j * 8 + 2 * tig;
        bA[j] = gbsum[n0 + c];
        bB[j] = gbsum[n0 + c + 1];
    }
    #pragma unroll
    for (int i = 0; i < 4; ++i) {
        const int r0 = wm + i * 16 + tg;
        float* o0 = out + (size_t)r0 * SSH + (size_t)s * HH + n0;
        float* o1 = o0 + (size_t)8 * SSH;
        #pragma unroll
        for (int j = 0; j < 4; ++j) {
            const int c = wn + j * 8 + 2 * tig;
            float2 v0 = make_float2(acc[i][j][0] + bA[j], acc[i][j][1] + bB[j]);
            float2 v1 = make_float2(acc[i][j][2] + bA[j], acc[i][j][3] + bB[j]);
            *reinterpret_cast<float2*>(o0 + c) = v0;
            *reinterpret_cast<float2*>(o1 + c) = v1;
        }
    }
}

extern "C" void kernel_launch(void* const* d_in, const int* in_sizes, int n_in,
                              void* d_out, int out_size)
{
    const float* x    = (const float*)d_in[0];   // [128, 513, 256]
    const float* W    = (const float*)d_in[1];   // [5, 256, 256]
    const float* bias = (const float*)d_in[2];   // [5, 256]
    float* out        = (float*)d_out;           // [128, 513, 4, 64]

    cvtw_kernel<<<(NCVT + 255) / 256, 256>>>(W, bias);

    cudaFuncSetAttribute(pmha_fused_kernel, cudaFuncAttributeMaxDynamicSharedMemorySize, SMTOT);
    dim3 grid(2, SSEQ);
    pmha_fused_kernel<<<grid, 256, SMTOT>>>(x, out);
}

// round 13
// speedup vs baseline: 1.0337x; 1.0337x over previous
#include <cuda_runtime.h>
#include <cuda_fp16.h>
#include <cstdint>

#define BB   128
#define SSEQ 513
#define HH   256
#define SSH  (SSEQ * HH)

#define NW    (5 * HH * HH)
#define NW16  (NW / 16)              // 20,480
#define NCVT  (NW16 + 32)

__device__ __half gw[NW];            // [widx][n][h] fp16
__device__ float  gbsum[HH];         // sum of 5 bias vectors

// ---------------- fused GEMM tiling ----------------
// X resident in smem: 128 rows x 256 fp16, 528B row stride (conflict-free ldmatrix)
#define XROWB 528
#define XSMB  (128 * XROWB)          // 67584
// W ring: k=64 tiles, 128 rows x 144B, 2 stages
#define KT    64
#define ROWB  144
#define TILEB (128 * ROWB)           // 18432
#define SMTOT (XSMB + 2 * TILEB)     // 104448
#define NUNIT 8                      // 2 n-halves x 4 k-tiles

__device__ __forceinline__ uint32_t smem_u32(const void* p) {
    uint32_t a;
    asm("{ .reg .u64 t; cvta.to.shared.u64 t, %1; cvt.u32.u64 %0, t; }" : "=r"(a) : "l"(p));
    return a;
}
__device__ __forceinline__ void cpasync16(uint32_t dst, const void* src) {
    asm volatile("cp.async.ca.shared.global [%0], [%1], 16;" :: "r"(dst), "l"(src));
}
__device__ __forceinline__ void cp_commit() { asm volatile("cp.async.commit_group;"); }
__device__ __forceinline__ void cp_wait0()  { asm volatile("cp.async.wait_group 0;"); }
__device__ __forceinline__ void ldsm_x4(uint32_t* r, uint32_t addr) {
    asm volatile("ldmatrix.sync.aligned.m8n8.x4.shared.b16 {%0,%1,%2,%3}, [%4];"
                 : "=r"(r[0]), "=r"(r[1]), "=r"(r[2]), "=r"(r[3]) : "r"(addr));
}
__device__ __forceinline__ void mma_f16(float* d, const uint32_t* a, uint32_t b0, uint32_t b1) {
    asm volatile(
        "mma.sync.aligned.m16n8k16.row.col.f32.f16.f16.f32 "
        "{%0,%1,%2,%3}, {%4,%5,%6,%7}, {%8,%9}, {%0,%1,%2,%3};"
        : "+f"(d[0]), "+f"(d[1]), "+f"(d[2]), "+f"(d[3])
        : "r"(a[0]), "r"(a[1]), "r"(a[2]), "r"(a[3]), "r"(b0), "r"(b1));
}
__device__ __forceinline__ uint2 f4_to_h4(float4 v) {
    __half2 h0 = __floats2half2_rn(v.x, v.y);
    __half2 h1 = __floats2half2_rn(v.z, v.w);
    uint2 u;
    u.x = *reinterpret_cast<uint32_t*>(&h0);
    u.y = *reinterpret_cast<uint32_t*>(&h1);
    return u;
}

// ---- kernel 1: W fp32->fp16 + bias presum (1.3MB, trivial) ----
__global__ __launch_bounds__(256)
void cvtw_kernel(const float* __restrict__ W, const float* __restrict__ bias)
{
    const uint32_t id = blockIdx.x * 256 + threadIdx.x;
    if (id < NW16) {
        const size_t f = (size_t)id * 16;
        const float4* wp = reinterpret_cast<const float4*>(W + f);
        float4 v0 = wp[0], v1 = wp[1], v2 = wp[2], v3 = wp[3];
        uint2 a = f4_to_h4(v0), b = f4_to_h4(v1);
        uint2 c = f4_to_h4(v2), d = f4_to_h4(v3);
        uint4* op = reinterpret_cast<uint4*>(&gw[f]);
        op[0] = make_uint4(a.x, a.y, b.x, b.y);
        op[1] = make_uint4(c.x, c.y, d.x, d.y);
    } else if (id < NCVT) {
        const int t = (int)(id - NW16);
        #pragma unroll
        for (int j = 0; j < 8; ++j) {
            const int c = t * 8 + j;
            float v = 0.0f;
            #pragma unroll
            for (int l = 0; l < 5; ++l) v += bias[l * HH + c];
            gbsum[c] = v;
        }
    }
}

// ---- fused kernel: ONE CTA per s, full N=256 in two halves, X converted once ----
// out[0:128, s, 0:256] = x[:,s,:] @ W[idx]^T + bsum
__global__ __launch_bounds__(256, 2)
void pmha_fused_kernel(const float* __restrict__ x, float* __restrict__ out)
{
    extern __shared__ char smem[];
    const uint32_t sb = smem_u32(smem);
    const uint32_t wbase = sb + XSMB;
    const int tid  = threadIdx.x;
    const int lane = tid & 31;
    const int wid  = tid >> 5;
    const int tg   = lane >> 2;
    const int tig  = lane & 3;
    const int wm   = (wid >> 2) * 64;
    const int wn   = (wid & 3) * 32;
    const int s    = blockIdx.x;
    const int widx = (s < 3) ? s : ((s & 1) ? 3 : 4);

    const float*  xsrc = x  + (size_t)s * HH;
    const __half* Wb   = gw + (size_t)widx * (HH * HH);

    // W prefetch for unit u: nh = u>>2 (n-half), kt = u&3 (k-tile), ring slot u&1
    const int prow = tid >> 3;
    const int pc   = tid & 7;
    auto prefetchW = [&](int u) {
        const int nh = u >> 2;
        const int k0 = (u & 3) * KT;
        const __half* Wp = Wb + (size_t)(nh * 128) * HH;
        const uint32_t base = wbase + (u & 1) * TILEB;
        #pragma unroll
        for (int t = 0; t < 4; ++t) {
            const int row = prow + t * 32;
            cpasync16(base + (uint32_t)row * ROWB + (uint32_t)pc * 16,
                      Wp + (size_t)row * HH + k0 + pc * 8);
        }
    };

    prefetchW(0); cp_commit();   // W unit 0 loads while X converts below

    // ---- one-time X conversion: 128x256 fp32 -> resident fp16 smem (MLP=8) ----
    {
        const int crow = tid >> 6;          // 0..3
        const int cc4  = tid & 63;          // float4 col 0..63
        #pragma unroll 8
        for (int p = 0; p < 32; ++p) {
            const int row = p * 4 + crow;
            float4 v = *reinterpret_cast<const float4*>(xsrc + (size_t)row * SSH + cc4 * 4);
            *reinterpret_cast<uint2*>(smem + (uint32_t)row * XROWB + (uint32_t)cc4 * 8) = f4_to_h4(v);
        }
    }

    // ldmatrix base addresses
    const int lr = lane & 15;
    const int lc = lane >> 4;
    uint32_t aA[4], aB[2];
    #pragma unroll
    for (int i = 0; i < 4; ++i)
        aA[i] = sb + (uint32_t)(wm + i * 16 + lr) * XROWB + lc * 16;
    #pragma unroll
    for (int jj = 0; jj < 2; ++jj)
        aB[jj] = wbase + (uint32_t)(wn + jj * 16 + lr) * ROWB + lc * 16;

    float acc[4][4][4] = {};

    // epilogue for one n-half
    auto epilogue = [&](int n0) {
        float bA[4], bB[4];
        #pragma unroll
        for (int j = 0; j < 4; ++j) {
            const int c = wn + j * 8 + 2 * tig;
            bA[j] = gbsum[n0 + c];
            bB[j] = gbsum[n0 + c + 1];
        }
        #pragma unroll
        for (int i = 0; i < 4; ++i) {
            const int r0 = wm + i * 16 + tg;
            float* o0 = out + (size_t)r0 * SSH + (size_t)s * HH + n0;
            float* o1 = o0 + (size_t)8 * SSH;
            #pragma unroll
            for (int j = 0; j < 4; ++j) {
                const int c = wn + j * 8 + 2 * tig;
                float2 v0 = make_float2(acc[i][j][0] + bA[j], acc[i][j][1] + bB[j]);
                float2 v1 = make_float2(acc[i][j][2] + bA[j], acc[i][j][3] + bB[j]);
                *reinterpret_cast<float2*>(o0 + c) = v0;
                *reinterpret_cast<float2*>(o1 + c) = v1;
            }
        }
    };

    #pragma unroll
    for (int u = 0; u < NUNIT; ++u) {
        cp_wait0();
        __syncthreads();     // first iter also publishes the X conversion

        if (u + 1 < NUNIT) { prefetchW(u + 1); cp_commit(); }

        const uint32_t wst = (u & 1) * TILEB;
        const uint32_t xkt = (uint32_t)(u & 3) * 128;   // 64 fp16 = 128B per k-tile
        #pragma unroll
        for (int ks = 0; ks < 4; ++ks) {
            uint32_t a[4][4], b[2][4];
            #pragma unroll
            for (int i = 0; i < 4; ++i) ldsm_x4(a[i], aA[i] + xkt + ks * 32);
            #pragma unroll
            for (int jj = 0; jj < 2; ++jj) ldsm_x4(b[jj], aB[jj] + wst + ks * 32);
            #pragma unroll
            for (int i = 0; i < 4; ++i)
                #pragma unroll
                for (int j = 0; j < 4; ++j) {
                    const int jj = j >> 1, sel = j & 1;
                    mma_f16(acc[i][j], a[i], b[jj][sel], b[jj][sel + 2]);
                }
        }

        if (u == 3) {        // n-half 0 complete: write it out, reset acc
            epilogue(0);
            #pragma unroll
            for (int i = 0; i < 4; ++i)
                #pragma unroll
                for (int j = 0; j < 4; ++j)
                    #pragma unroll
                    for (int q = 0; q < 4; ++q) acc[i][j][q] = 0.0f;
        }
    }
    epilogue(128);
}

extern "C" void kernel_launch(void* const* d_in, const int* in_sizes, int n_in,
                              void* d_out, int out_size)
{
    const float* x    = (const float*)d_in[0];   // [128, 513, 256]
    const float* W    = (const float*)d_in[1];   // [5, 256, 256]
    const float* bias = (const float*)d_in[2];   // [5, 256]
    float* out        = (float*)d_out;           // [128, 513, 4, 64]

    cvtw_kernel<<<(NCVT + 255) / 256, 256>>>(W, bias);

    cudaFuncSetAttribute(pmha_fused_kernel, cudaFuncAttributeMaxDynamicSharedMemorySize, SMTOT);
    pmha_fused_kernel<<<SSEQ, 256, SMTOT>>>(x, out);
}